// round 16
// baseline (speedup 1.0000x reference)
#include <cuda_runtime.h>
#include <cstdint>
#include <math.h>

// Problem constants
constexpr int cB   = 32;
constexpr int cN   = 256;
constexpr int cCIN = 64;
constexpr int cCH  = 128;   // C_H == C_OUT
constexpr int cR   = 5;
constexpr int cJR  = cN * cR;       // 1280
constexpr int cJQ  = cJR / 4;       // 320 per chunk
constexpr int cXD  = 1024;

constexpr int MASK_WORDS_PER_ROW = cJR / 32;  // 40
constexpr int MASK_WORDS_Q       = cJQ / 32;  // 10
constexpr int ATTN_TILE_I = 32;                // i-rows per block
constexpr int N_ITILES = cN / ATTN_TILE_I;     // 8
constexpr int P_STRIDE = 36;                   // padded stride of s_p [jr_local][row]
constexpr int TILE_JR = 8;                     // H rows per stage
constexpr int N_STAGES = 3;
constexpr int N_TILES_TOTAL = cJR / TILE_JR;   // 160 (ring flows across chunks)
constexpr int N_TILES_Q     = cJQ / TILE_JR;   // 40

// smem floats: s_p 320*36 + s_dst 320 + s_src 160 + s_inv 32 + s_mask 320 + s_h 3*8*128
constexpr int ATTN_SMEM = (cJQ * P_STRIDE + cJQ + ATTN_TILE_I * cR + ATTN_TILE_I
                           + ATTN_TILE_I * MASK_WORDS_Q
                           + N_STAGES * TILE_JR * cCH) * 4;   // 61,696 B -> 3 blocks/SM

// ---------------- device scratch (no cudaMalloc allowed) ----------------
__device__ float    g_h[cB * cN * cR * cCH];            // (b, jr, c): 8192 x 640
__device__ float    g_atoms[cB * cN * cCH];             // layer activations (b,n,c)
__device__ float    g_src[cB * cN * cR];
__device__ float    g_dst[cB * cN * cR];
__device__ unsigned g_mask[cB * cN * MASK_WORDS_PER_ROW];
__device__ float    g_pool[cB * 2 * cCH];               // [mean(128) | max(128)] per batch

__device__ __forceinline__ float leaky(float v) { return v >= 0.f ? v : 0.2f * v; }

__device__ __forceinline__ void cp_async16(unsigned int smem_dst, const void* gsrc) {
    asm volatile("cp.async.cg.shared.global [%0], [%1], 16;\n" :: "r"(smem_dst), "l"(gsrc));
}
__device__ __forceinline__ void cp_commit() {
    asm volatile("cp.async.commit_group;\n");
}
template <int N>
__device__ __forceinline__ void cp_wait() {
    asm volatile("cp.async.wait_group %0;\n" :: "n"(N));
}

// packed f32x2 helpers (Blackwell FFMA2 path — PTX only)
__device__ __forceinline__ unsigned long long pack2(float lo, float hi) {
    unsigned long long r;
    asm("mov.b64 %0, {%1, %2};" : "=l"(r) : "f"(lo), "f"(hi));
    return r;
}
__device__ __forceinline__ void fma2(unsigned long long& d, unsigned long long a,
                                     unsigned long long b) {
    asm("fma.rn.f32x2 %0, %1, %2, %0;" : "+l"(d) : "l"(a), "l"(b));
}
__device__ __forceinline__ float2 unpack2(unsigned long long v) {
    float2 r;
    asm("mov.b64 {%0, %1}, %2;" : "=f"(r.x), "=f"(r.y) : "l"(v));
    return r;
}

// ---------------- 1) pack bond mask into bits ----------------
__global__ __launch_bounds__(256) void pack_mask_kernel(const int* __restrict__ bonds) {
    int w = blockIdx.x * blockDim.x + threadIdx.x;
    if (w >= cB * cN * MASK_WORDS_PER_ROW) return;
    const int4* p = reinterpret_cast<const int4*>(bonds) + w * 8;
    unsigned m = 0;
#pragma unroll
    for (int q = 0; q < 8; q++) {
        int4 v = p[q];
        m |= (v.x == 1 ? 1u : 0u) << (q * 4 + 0);
        m |= (v.y == 1 ? 1u : 0u) << (q * 4 + 1);
        m |= (v.z == 1 ? 1u : 0u) << (q * 4 + 2);
        m |= (v.w == 1 ? 1u : 0u) << (q * 4 + 3);
    }
    g_mask[w] = m;
}

// ---------------- 2) h = A @ W + bias   (M=8192, N=640, K=64/128) ----------------
// R12 GEMM: 128x64 block tile, 8 rows x 4 cols per thread, f32x2 accumulators,
// register-staged double buffer, ONE __syncthreads per 16-k tile.
template <int K>
__global__ __launch_bounds__(256) void gemm_bias_kernel(const float* __restrict__ A,
                                                        const float* __restrict__ W,
                                                        const float* __restrict__ bias) {
    __shared__ float As[2][16][132];
    __shared__ float Bs[2][16][68];
    const int t  = threadIdx.x;
    const int tx = t & 15, ty = t >> 4;
    const int bm = blockIdx.y * 128, bn = blockIdx.x * 64;

    const int arow = t & 127;
    const int aq   = (t >> 7) * 2;
    const int wkr  = t >> 4, wn4 = t & 15;

    unsigned long long acc[4][4];
#pragma unroll
    for (int i = 0; i < 4; i++)
#pragma unroll
        for (int j = 0; j < 4; j++) acc[i][j] = 0ull;

    float4 av0 = *reinterpret_cast<const float4*>(&A[(bm + arow) * K + aq * 4]);
    float4 av1 = *reinterpret_cast<const float4*>(&A[(bm + arow) * K + (aq + 1) * 4]);
    float4 wv  = *reinterpret_cast<const float4*>(&W[wkr * 640 + bn + wn4 * 4]);
    As[0][aq * 4 + 0][arow] = av0.x; As[0][aq * 4 + 1][arow] = av0.y;
    As[0][aq * 4 + 2][arow] = av0.z; As[0][aq * 4 + 3][arow] = av0.w;
    As[0][aq * 4 + 4][arow] = av1.x; As[0][aq * 4 + 5][arow] = av1.y;
    As[0][aq * 4 + 6][arow] = av1.z; As[0][aq * 4 + 7][arow] = av1.w;
    *reinterpret_cast<float4*>(&Bs[0][wkr][wn4 * 4]) = wv;
    __syncthreads();

    for (int bk = 0; bk < K; bk += 16) {
        const int buf = (bk >> 4) & 1;
        const bool more = (bk + 16 < K);
        if (more) {
            av0 = *reinterpret_cast<const float4*>(&A[(bm + arow) * K + bk + 16 + aq * 4]);
            av1 = *reinterpret_cast<const float4*>(&A[(bm + arow) * K + bk + 16 + (aq + 1) * 4]);
            wv  = *reinterpret_cast<const float4*>(&W[(bk + 16 + wkr) * 640 + bn + wn4 * 4]);
        }
#pragma unroll
        for (int k = 0; k < 16; k++) {
            float4 a0 = *reinterpret_cast<float4*>(&As[buf][k][ty * 8]);
            float4 a1 = *reinterpret_cast<float4*>(&As[buf][k][ty * 8 + 4]);
            float4 bv = *reinterpret_cast<float4*>(&Bs[buf][k][tx * 4]);
            unsigned long long pa0 = pack2(a0.x, a0.y);
            unsigned long long pa1 = pack2(a0.z, a0.w);
            unsigned long long pa2 = pack2(a1.x, a1.y);
            unsigned long long pa3 = pack2(a1.z, a1.w);
            unsigned long long pb0 = pack2(bv.x, bv.x);
            unsigned long long pb1 = pack2(bv.y, bv.y);
            unsigned long long pb2 = pack2(bv.z, bv.z);
            unsigned long long pb3 = pack2(bv.w, bv.w);
            fma2(acc[0][0], pa0, pb0); fma2(acc[0][1], pa0, pb1);
            fma2(acc[0][2], pa0, pb2); fma2(acc[0][3], pa0, pb3);
            fma2(acc[1][0], pa1, pb0); fma2(acc[1][1], pa1, pb1);
            fma2(acc[1][2], pa1, pb2); fma2(acc[1][3], pa1, pb3);
            fma2(acc[2][0], pa2, pb0); fma2(acc[2][1], pa2, pb1);
            fma2(acc[2][2], pa2, pb2); fma2(acc[2][3], pa2, pb3);
            fma2(acc[3][0], pa3, pb0); fma2(acc[3][1], pa3, pb1);
            fma2(acc[3][2], pa3, pb2); fma2(acc[3][3], pa3, pb3);
        }
        if (more) {
            const int nb = buf ^ 1;
            As[nb][aq * 4 + 0][arow] = av0.x; As[nb][aq * 4 + 1][arow] = av0.y;
            As[nb][aq * 4 + 2][arow] = av0.z; As[nb][aq * 4 + 3][arow] = av0.w;
            As[nb][aq * 4 + 4][arow] = av1.x; As[nb][aq * 4 + 5][arow] = av1.y;
            As[nb][aq * 4 + 6][arow] = av1.z; As[nb][aq * 4 + 7][arow] = av1.w;
            *reinterpret_cast<float4*>(&Bs[nb][wkr][wn4 * 4]) = wv;
        }
        __syncthreads();
    }

    float4 bb = *reinterpret_cast<const float4*>(&bias[bn + tx * 4]);
    const float bias4[4] = {bb.x, bb.y, bb.z, bb.w};
#pragma unroll
    for (int i = 0; i < 4; i++) {
        float o0[4], o1[4];
#pragma unroll
        for (int j = 0; j < 4; j++) {
            float2 v = unpack2(acc[i][j]);
            o0[j] = v.x + bias4[j];
            o1[j] = v.y + bias4[j];
        }
        const int r0 = bm + ty * 8 + 2 * i;
        *reinterpret_cast<float4*>(&g_h[(size_t)r0 * 640 + bn + tx * 4]) =
            make_float4(o0[0], o0[1], o0[2], o0[3]);
        *reinterpret_cast<float4*>(&g_h[(size_t)(r0 + 1) * 640 + bn + tx * 4]) =
            make_float4(o1[0], o1[1], o1[2], o1[3]);
    }
}

// ---------------- 3) src/dst projections ----------------
__global__ __launch_bounds__(160) void src_dst_kernel(const float* __restrict__ a) {
    const int bn   = blockIdx.x;
    const int r    = threadIdx.x >> 5;
    const int lane = threadIdx.x & 31;
    const float* hrow = &g_h[((size_t)bn * cR + r) * cCH];
    float4 hv = *reinterpret_cast<const float4*>(&hrow[lane * 4]);
    float4 as = *reinterpret_cast<const float4*>(&a[r * (2 * cCH) + lane * 4]);
    float4 ad = *reinterpret_cast<const float4*>(&a[r * (2 * cCH) + cCH + lane * 4]);
    float s = hv.x * as.x + hv.y * as.y + hv.z * as.z + hv.w * as.w;
    float d = hv.x * ad.x + hv.y * ad.y + hv.z * ad.z + hv.w * ad.w;
#pragma unroll
    for (int o = 16; o; o >>= 1) {
        s += __shfl_xor_sync(0xffffffffu, s, o);
        d += __shfl_xor_sync(0xffffffffu, d, o);
    }
    if (lane == 0) {
        g_src[bn * cR + r] = s;
        g_dst[bn * cR + r] = d;
    }
}

// ---------------- 4) fused masked softmax + aggregation, jr-chunked x4 --------
// Block: (b, 32-row i-tile), 256 threads. jr processed in FOUR 320 chunks
// sequentially, reusing one 46KB s_p -> 61.7KB smem -> 3 blocks/SM.
// Identical math / sum order to R13 (bit-exact). Accumulators and row sums
// persist in registers across chunks; 3-stage cp.async ring of 8-row H tiles
// flows continuously across chunk boundaries, ONE __syncthreads per tile.
template <bool LEAKY_OUT>
__global__ __launch_bounds__(256) void attn_kernel() {
    extern __shared__ float sm[];
    float*    s_p    = sm;                               // [320][36] transposed
    float*    s_dst  = s_p + cJQ * P_STRIDE;             // 320 (current chunk)
    float*    s_src  = s_dst + cJQ;                      // 160
    float*    s_inv  = s_src + ATTN_TILE_I * cR;         // 32
    unsigned* s_mask = reinterpret_cast<unsigned*>(s_inv + ATTN_TILE_I); // 320 words
    float*    s_h    = reinterpret_cast<float*>(s_mask + ATTN_TILE_I * MASK_WORDS_Q);
                                                         // 3*8*128 (16B aligned)

    const int b  = blockIdx.x >> 3;
    const int i0 = (blockIdx.x & 7) * ATTN_TILE_I;
    const int t  = threadIdx.x;

    const float* hbase = &g_h[(size_t)b * cJR * cCH];
    const unsigned s_h_addr = (unsigned)__cvta_generic_to_shared(s_h);
    const int prow = t >> 5, pc4 = t & 31;    // 8 rows x 32 quad-cols = one 8x128 tile

    // prefetch tiles 0,1 (one cp_async16 per thread per tile)
#pragma unroll
    for (int tt = 0; tt < 2; tt++) {
        cp_async16(s_h_addr + (tt % N_STAGES) * (TILE_JR * cCH * 4)
                       + (prow * cCH + pc4 * 4) * 4,
                   hbase + (tt * TILE_JR + prow) * cCH + pc4 * 4);
        cp_commit();
    }

    if (t < ATTN_TILE_I * cR) s_src[t] = g_src[(b * cN + i0) * cR + t];

    const int p1row = t >> 3, p1l8 = t & 7;   // phase-1 mapping
    unsigned long long acc[4][2];             // phase-2 accumulators (persist chunks)
#pragma unroll
    for (int i = 0; i < 4; i++) { acc[i][0] = 0ull; acc[i][1] = 0ull; }
    float sum = 0.f;                          // row partial sum (persists chunks)

    const int c4 = t & 31;                    // phase-2: cols c4*4..+3
    const int rg = t >> 5;                    // phase-2: warp -> rows rg*4..+3
    const float* pbase = s_p + rg * 4;

    for (int chunk = 0; chunk < 4; chunk++) {
        // load this chunk's dst + mask (s_src loaded once above)
        for (int idx = t; idx < cJQ; idx += 256)
            s_dst[idx] = g_dst[b * cJR + chunk * cJQ + idx];
        for (int idx = t; idx < ATTN_TILE_I * MASK_WORDS_Q; idx += 256)   // 320 words!
            s_mask[idx] = g_mask[(b * cN + i0 + (idx / MASK_WORDS_Q)) * MASK_WORDS_PER_ROW
                                 + chunk * MASK_WORDS_Q + (idx % MASK_WORDS_Q)];
        __syncthreads();   // dst/mask ready; also gates s_p reuse (chunk-end bar)

        // ---- phase 1 (8 threads / row): single pass, no max-subtraction
        {
            const float* srcr = s_src + p1row * cR;
            const unsigned* mrow = s_mask + p1row * MASK_WORDS_Q;
            int r = p1l8 % 5;                  // 320 % 5 == 0: local e%5 == global jr%5
            for (int e = p1l8; e < cJQ; e += 8) {
                float v = leaky(srcr[r] + s_dst[e]);
                unsigned bit = (mrow[e >> 5] >> (e & 31)) & 1u;
                float p = bit ? __expf(v) : 0.f;
                s_p[e * P_STRIDE + p1row] = p;
                sum += p;
                r += 3; if (r >= 5) r -= 5;
            }
            if (chunk == 3) {                  // final sum reduce -> s_inv
                float sred = sum;
#pragma unroll
                for (int o = 4; o; o >>= 1) sred += __shfl_xor_sync(0xffffffffu, sred, o);
                if (p1l8 == 0) s_inv[p1row] = 1.f / sred;
            }
        }

        // ---- phase 2 over this chunk's 40 tiles (ring continues across chunks)
        for (int local = 0; local < N_TILES_Q; local++) {
            const int tt = chunk * N_TILES_Q + local;
            cp_wait<1>();
            __syncthreads();   // tile tt ready; phase-1 writes visible; tile tt-1 done
            if (tt + 2 < N_TILES_TOTAL) {
                const int pf = tt + 2;
                cp_async16(s_h_addr + (pf % N_STAGES) * (TILE_JR * cCH * 4)
                               + (prow * cCH + pc4 * 4) * 4,
                           hbase + (pf * TILE_JR + prow) * cCH + pc4 * 4);
            }
            cp_commit();       // exactly one group per iteration

            const float* hh = s_h + (tt % N_STAGES) * (TILE_JR * cCH) + c4 * 4;
            const float* pp = pbase + local * TILE_JR * P_STRIDE;
#pragma unroll
            for (int j = 0; j < TILE_JR; j++) {
                float4 p4 = *reinterpret_cast<const float4*>(pp);  // warp-uniform bcast
                ulonglong2 hv = *reinterpret_cast<const ulonglong2*>(hh);
                unsigned long long pa;
                pa = pack2(p4.x, p4.x); fma2(acc[0][0], pa, hv.x); fma2(acc[0][1], pa, hv.y);
                pa = pack2(p4.y, p4.y); fma2(acc[1][0], pa, hv.x); fma2(acc[1][1], pa, hv.y);
                pa = pack2(p4.z, p4.z); fma2(acc[2][0], pa, hv.x); fma2(acc[2][1], pa, hv.y);
                pa = pack2(p4.w, p4.w); fma2(acc[3][0], pa, hv.x); fma2(acc[3][1], pa, hv.y);
                pp += P_STRIDE;
                hh += cCH;
            }
        }
        __syncthreads();       // all reads of s_p/s_dst done before next chunk rewrites
    }

    // ---- epilogue: normalize by total sums, optional leaky, store
#pragma unroll
    for (int i = 0; i < 4; i++) {
        const int row = rg * 4 + i;
        const float inv = s_inv[row];
        float2 lo = unpack2(acc[i][0]), hi = unpack2(acc[i][1]);
        float4 o = {lo.x * inv, lo.y * inv, hi.x * inv, hi.y * inv};
        if (LEAKY_OUT) {
            o.x = leaky(o.x); o.y = leaky(o.y); o.z = leaky(o.z); o.w = leaky(o.w);
        }
        *reinterpret_cast<float4*>(&g_atoms[(b * cN + i0 + row) * cCH + c4 * 4]) = o;
    }
}

// ---------------- 5) mean/max pooling over nodes ----------------
__global__ __launch_bounds__(512) void pool_kernel() {
    __shared__ float s_sum[4][cCH];
    __shared__ float s_max[4][cCH];
    const int b  = blockIdx.x;
    const int c  = threadIdx.x & 127;
    const int ch = threadIdx.x >> 7;
    float sum = 0.f, mx = -3.4e38f;
    for (int n = ch * 64; n < ch * 64 + 64; n++) {
        float v = g_atoms[(b * cN + n) * cCH + c];
        sum += v;
        mx = fmaxf(mx, v);
    }
    s_sum[ch][c] = sum;
    s_max[ch][c] = mx;
    __syncthreads();
    if (ch == 0) {
        sum = (s_sum[0][c] + s_sum[1][c]) + (s_sum[2][c] + s_sum[3][c]);
        mx = fmaxf(fmaxf(s_max[0][c], s_max[1][c]), fmaxf(s_max[2][c], s_max[3][c]));
        g_pool[b * 256 + c] = sum * (1.f / 256.f);
        g_pool[b * 256 + cCH + c] = mx;
    }
}

// ---------------- 6) final MLP (block per batch) ----------------
__global__ __launch_bounds__(256) void mlp_kernel(const float* __restrict__ x,
                                                  const float* __restrict__ We1, const float* __restrict__ be1,
                                                  const float* __restrict__ We2, const float* __restrict__ be2,
                                                  const float* __restrict__ We3, const float* __restrict__ be3,
                                                  float* __restrict__ out) {
    __shared__ float s_z[cXD + 256];
    __shared__ float s_h1[256];
    __shared__ float s_h2[32];
    const int b = blockIdx.x, t = threadIdx.x;
    for (int i = t; i < cXD; i += 256) s_z[i] = x[b * cXD + i];
    s_z[cXD + t] = g_pool[b * 256 + t];
    __syncthreads();
    {
        float a0 = 0.f, a1 = 0.f, a2 = 0.f, a3 = 0.f;
#pragma unroll 2
        for (int k = 0; k < cXD + 256; k += 4) {
            a0 += s_z[k + 0] * We1[(k + 0) * 256 + t];
            a1 += s_z[k + 1] * We1[(k + 1) * 256 + t];
            a2 += s_z[k + 2] * We1[(k + 2) * 256 + t];
            a3 += s_z[k + 3] * We1[(k + 3) * 256 + t];
        }
        float v = (a0 + a1) + (a2 + a3) + be1[t];
        s_h1[t] = leaky(v);
    }
    __syncthreads();
    if (t < 32) {
        float c0 = 0.f, c1 = 0.f, c2 = 0.f, c3 = 0.f;
        for (int k = 0; k < 256; k += 4) {
            c0 += s_h1[k + 0] * We2[(k + 0) * 32 + t];
            c1 += s_h1[k + 1] * We2[(k + 1) * 32 + t];
            c2 += s_h1[k + 2] * We2[(k + 2) * 32 + t];
            c3 += s_h1[k + 3] * We2[(k + 3) * 32 + t];
        }
        float u = (c0 + c1) + (c2 + c3) + be2[t];
        s_h2[t] = leaky(u);
    }
    __syncthreads();
    if (t < 32) {
        float p = s_h2[t] * We3[t];
#pragma unroll
        for (int o = 16; o; o >>= 1) p += __shfl_xor_sync(0xffffffffu, p, o);
        if (t == 0) out[b] = p + be3[0];
    }
}

// ---------------- launch ----------------
extern "C" void kernel_launch(void* const* d_in, const int* in_sizes, int n_in,
                              void* d_out, int out_size) {
    const float* x       = (const float*)d_in[0];
    const float* y_atoms = (const float*)d_in[1];
    const int*   y_bonds = (const int*)d_in[2];
    const float* W1 = (const float*)d_in[3];
    const float* b1 = (const float*)d_in[4];
    const float* a1 = (const float*)d_in[5];
    const float* W2 = (const float*)d_in[6];
    const float* b2 = (const float*)d_in[7];
    const float* a2 = (const float*)d_in[8];
    const float* W3 = (const float*)d_in[9];
    const float* b3 = (const float*)d_in[10];
    const float* a3 = (const float*)d_in[11];
    const float* We1 = (const float*)d_in[12];
    const float* be1 = (const float*)d_in[13];
    const float* We2 = (const float*)d_in[14];
    const float* be2 = (const float*)d_in[15];
    const float* We3 = (const float*)d_in[16];
    const float* be3 = (const float*)d_in[17];
    float* out = (float*)d_out;

    cudaFuncSetAttribute((const void*)attn_kernel<true>,
                         cudaFuncAttributeMaxDynamicSharedMemorySize, ATTN_SMEM);
    cudaFuncSetAttribute((const void*)attn_kernel<false>,
                         cudaFuncAttributeMaxDynamicSharedMemorySize, ATTN_SMEM);

    float* atoms_ptr = nullptr;
    cudaGetSymbolAddress((void**)&atoms_ptr, g_atoms);

    const dim3 gemm_grid(10, 64);          // 128x64 tiles over 8192x640
    const int attn_grid = cB * N_ITILES;   // 256

    pack_mask_kernel<<<(cB * cN * MASK_WORDS_PER_ROW + 255) / 256, 256>>>(y_bonds);

    // layer 1
    gemm_bias_kernel<cCIN><<<gemm_grid, 256>>>(y_atoms, W1, b1);
    src_dst_kernel<<<cB * cN, 160>>>(a1);
    attn_kernel<true><<<attn_grid, 256, ATTN_SMEM>>>();
    // layer 2
    gemm_bias_kernel<cCH><<<gemm_grid, 256>>>(atoms_ptr, W2, b2);
    src_dst_kernel<<<cB * cN, 160>>>(a2);
    attn_kernel<true><<<attn_grid, 256, ATTN_SMEM>>>();
    // layer 3
    gemm_bias_kernel<cCH><<<gemm_grid, 256>>>(atoms_ptr, W3, b3);
    src_dst_kernel<<<cB * cN, 160>>>(a3);
    attn_kernel<false><<<attn_grid, 256, ATTN_SMEM>>>();

    pool_kernel<<<cB, 512>>>();
    mlp_kernel<<<cB, 256>>>(x, We1, be1, We2, be2, We3, be3, out);
}

// round 17
// speedup vs baseline: 1.0136x; 1.0136x over previous
#include <cuda_runtime.h>
#include <cstdint>
#include <math.h>

// Problem constants
constexpr int cB   = 32;
constexpr int cN   = 256;
constexpr int cCIN = 64;
constexpr int cCH  = 128;   // C_H == C_OUT
constexpr int cR   = 5;
constexpr int cJR  = cN * cR;       // 1280
constexpr int cJQ  = cJR / 4;       // 320 per chunk
constexpr int cXD  = 1024;

constexpr int MASK_WORDS_PER_ROW = cJR / 32;  // 40
constexpr int MASK_WORDS_Q       = cJQ / 32;  // 10
constexpr int ATTN_TILE_I = 32;                // i-rows per block
constexpr int N_ITILES = cN / ATTN_TILE_I;     // 8
constexpr int P_STRIDE = 36;                   // padded stride of s_p [jr_local][row]
constexpr int TILE_JR = 16;                    // H rows per stage (R17: 8 -> 16)
constexpr int N_STAGES = 3;
constexpr int N_TILES_TOTAL = cJR / TILE_JR;   // 80 (ring flows across chunks)
constexpr int N_TILES_Q     = cJQ / TILE_JR;   // 20

// smem floats: s_p 320*36 + s_dst 320 + s_src 160 + s_inv 32 + s_mask 320 + s_h 3*16*128
constexpr int ATTN_SMEM = (cJQ * P_STRIDE + cJQ + ATTN_TILE_I * cR + ATTN_TILE_I
                           + ATTN_TILE_I * MASK_WORDS_Q
                           + N_STAGES * TILE_JR * cCH) * 4;   // 73,984 B -> 2 blocks/SM

// ---------------- device scratch (no cudaMalloc allowed) ----------------
__device__ float    g_h[cB * cN * cR * cCH];            // (b, jr, c): 8192 x 640
__device__ float    g_atoms[cB * cN * cCH];             // layer activations (b,n,c)
__device__ float    g_src[cB * cN * cR];
__device__ float    g_dst[cB * cN * cR];
__device__ unsigned g_mask[cB * cN * MASK_WORDS_PER_ROW];
__device__ float    g_pool[cB * 2 * cCH];               // [mean(128) | max(128)] per batch

__device__ __forceinline__ float leaky(float v) { return v >= 0.f ? v : 0.2f * v; }

__device__ __forceinline__ void cp_async16(unsigned int smem_dst, const void* gsrc) {
    asm volatile("cp.async.cg.shared.global [%0], [%1], 16;\n" :: "r"(smem_dst), "l"(gsrc));
}
__device__ __forceinline__ void cp_commit() {
    asm volatile("cp.async.commit_group;\n");
}
template <int N>
__device__ __forceinline__ void cp_wait() {
    asm volatile("cp.async.wait_group %0;\n" :: "n"(N));
}

// packed f32x2 helpers (Blackwell FFMA2 path — PTX only)
__device__ __forceinline__ unsigned long long pack2(float lo, float hi) {
    unsigned long long r;
    asm("mov.b64 %0, {%1, %2};" : "=l"(r) : "f"(lo), "f"(hi));
    return r;
}
__device__ __forceinline__ void fma2(unsigned long long& d, unsigned long long a,
                                     unsigned long long b) {
    asm("fma.rn.f32x2 %0, %1, %2, %0;" : "+l"(d) : "l"(a), "l"(b));
}
__device__ __forceinline__ float2 unpack2(unsigned long long v) {
    float2 r;
    asm("mov.b64 {%0, %1}, %2;" : "=f"(r.x), "=f"(r.y) : "l"(v));
    return r;
}

// ---------------- 1) pack bond mask into bits ----------------
__global__ __launch_bounds__(256) void pack_mask_kernel(const int* __restrict__ bonds) {
    int w = blockIdx.x * blockDim.x + threadIdx.x;
    if (w >= cB * cN * MASK_WORDS_PER_ROW) return;
    const int4* p = reinterpret_cast<const int4*>(bonds) + w * 8;
    unsigned m = 0;
#pragma unroll
    for (int q = 0; q < 8; q++) {
        int4 v = p[q];
        m |= (v.x == 1 ? 1u : 0u) << (q * 4 + 0);
        m |= (v.y == 1 ? 1u : 0u) << (q * 4 + 1);
        m |= (v.z == 1 ? 1u : 0u) << (q * 4 + 2);
        m |= (v.w == 1 ? 1u : 0u) << (q * 4 + 3);
    }
    g_mask[w] = m;
}

// ---------------- 2) h = A @ W + bias   (M=8192, N=640, K=64/128) ----------------
// R12 GEMM: 128x64 block tile, 8 rows x 4 cols per thread, f32x2 accumulators,
// register-staged double buffer, ONE __syncthreads per 16-k tile.
template <int K>
__global__ __launch_bounds__(256) void gemm_bias_kernel(const float* __restrict__ A,
                                                        const float* __restrict__ W,
                                                        const float* __restrict__ bias) {
    __shared__ float As[2][16][132];
    __shared__ float Bs[2][16][68];
    const int t  = threadIdx.x;
    const int tx = t & 15, ty = t >> 4;
    const int bm = blockIdx.y * 128, bn = blockIdx.x * 64;

    const int arow = t & 127;
    const int aq   = (t >> 7) * 2;
    const int wkr  = t >> 4, wn4 = t & 15;

    unsigned long long acc[4][4];
#pragma unroll
    for (int i = 0; i < 4; i++)
#pragma unroll
        for (int j = 0; j < 4; j++) acc[i][j] = 0ull;

    float4 av0 = *reinterpret_cast<const float4*>(&A[(bm + arow) * K + aq * 4]);
    float4 av1 = *reinterpret_cast<const float4*>(&A[(bm + arow) * K + (aq + 1) * 4]);
    float4 wv  = *reinterpret_cast<const float4*>(&W[wkr * 640 + bn + wn4 * 4]);
    As[0][aq * 4 + 0][arow] = av0.x; As[0][aq * 4 + 1][arow] = av0.y;
    As[0][aq * 4 + 2][arow] = av0.z; As[0][aq * 4 + 3][arow] = av0.w;
    As[0][aq * 4 + 4][arow] = av1.x; As[0][aq * 4 + 5][arow] = av1.y;
    As[0][aq * 4 + 6][arow] = av1.z; As[0][aq * 4 + 7][arow] = av1.w;
    *reinterpret_cast<float4*>(&Bs[0][wkr][wn4 * 4]) = wv;
    __syncthreads();

    for (int bk = 0; bk < K; bk += 16) {
        const int buf = (bk >> 4) & 1;
        const bool more = (bk + 16 < K);
        if (more) {
            av0 = *reinterpret_cast<const float4*>(&A[(bm + arow) * K + bk + 16 + aq * 4]);
            av1 = *reinterpret_cast<const float4*>(&A[(bm + arow) * K + bk + 16 + (aq + 1) * 4]);
            wv  = *reinterpret_cast<const float4*>(&W[(bk + 16 + wkr) * 640 + bn + wn4 * 4]);
        }
#pragma unroll
        for (int k = 0; k < 16; k++) {
            float4 a0 = *reinterpret_cast<float4*>(&As[buf][k][ty * 8]);
            float4 a1 = *reinterpret_cast<float4*>(&As[buf][k][ty * 8 + 4]);
            float4 bv = *reinterpret_cast<float4*>(&Bs[buf][k][tx * 4]);
            unsigned long long pa0 = pack2(a0.x, a0.y);
            unsigned long long pa1 = pack2(a0.z, a0.w);
            unsigned long long pa2 = pack2(a1.x, a1.y);
            unsigned long long pa3 = pack2(a1.z, a1.w);
            unsigned long long pb0 = pack2(bv.x, bv.x);
            unsigned long long pb1 = pack2(bv.y, bv.y);
            unsigned long long pb2 = pack2(bv.z, bv.z);
            unsigned long long pb3 = pack2(bv.w, bv.w);
            fma2(acc[0][0], pa0, pb0); fma2(acc[0][1], pa0, pb1);
            fma2(acc[0][2], pa0, pb2); fma2(acc[0][3], pa0, pb3);
            fma2(acc[1][0], pa1, pb0); fma2(acc[1][1], pa1, pb1);
            fma2(acc[1][2], pa1, pb2); fma2(acc[1][3], pa1, pb3);
            fma2(acc[2][0], pa2, pb0); fma2(acc[2][1], pa2, pb1);
            fma2(acc[2][2], pa2, pb2); fma2(acc[2][3], pa2, pb3);
            fma2(acc[3][0], pa3, pb0); fma2(acc[3][1], pa3, pb1);
            fma2(acc[3][2], pa3, pb2); fma2(acc[3][3], pa3, pb3);
        }
        if (more) {
            const int nb = buf ^ 1;
            As[nb][aq * 4 + 0][arow] = av0.x; As[nb][aq * 4 + 1][arow] = av0.y;
            As[nb][aq * 4 + 2][arow] = av0.z; As[nb][aq * 4 + 3][arow] = av0.w;
            As[nb][aq * 4 + 4][arow] = av1.x; As[nb][aq * 4 + 5][arow] = av1.y;
            As[nb][aq * 4 + 6][arow] = av1.z; As[nb][aq * 4 + 7][arow] = av1.w;
            *reinterpret_cast<float4*>(&Bs[nb][wkr][wn4 * 4]) = wv;
        }
        __syncthreads();
    }

    float4 bb = *reinterpret_cast<const float4*>(&bias[bn + tx * 4]);
    const float bias4[4] = {bb.x, bb.y, bb.z, bb.w};
#pragma unroll
    for (int i = 0; i < 4; i++) {
        float o0[4], o1[4];
#pragma unroll
        for (int j = 0; j < 4; j++) {
            float2 v = unpack2(acc[i][j]);
            o0[j] = v.x + bias4[j];
            o1[j] = v.y + bias4[j];
        }
        const int r0 = bm + ty * 8 + 2 * i;
        *reinterpret_cast<float4*>(&g_h[(size_t)r0 * 640 + bn + tx * 4]) =
            make_float4(o0[0], o0[1], o0[2], o0[3]);
        *reinterpret_cast<float4*>(&g_h[(size_t)(r0 + 1) * 640 + bn + tx * 4]) =
            make_float4(o1[0], o1[1], o1[2], o1[3]);
    }
}

// ---------------- 3) src/dst projections ----------------
__global__ __launch_bounds__(160) void src_dst_kernel(const float* __restrict__ a) {
    const int bn   = blockIdx.x;
    const int r    = threadIdx.x >> 5;
    const int lane = threadIdx.x & 31;
    const float* hrow = &g_h[((size_t)bn * cR + r) * cCH];
    float4 hv = *reinterpret_cast<const float4*>(&hrow[lane * 4]);
    float4 as = *reinterpret_cast<const float4*>(&a[r * (2 * cCH) + lane * 4]);
    float4 ad = *reinterpret_cast<const float4*>(&a[r * (2 * cCH) + cCH + lane * 4]);
    float s = hv.x * as.x + hv.y * as.y + hv.z * as.z + hv.w * as.w;
    float d = hv.x * ad.x + hv.y * ad.y + hv.z * ad.z + hv.w * ad.w;
#pragma unroll
    for (int o = 16; o; o >>= 1) {
        s += __shfl_xor_sync(0xffffffffu, s, o);
        d += __shfl_xor_sync(0xffffffffu, d, o);
    }
    if (lane == 0) {
        g_src[bn * cR + r] = s;
        g_dst[bn * cR + r] = d;
    }
}

// ---------------- 4) fused masked softmax + aggregation, jr-chunked x4 --------
// Block: (b, 32-row i-tile), 256 threads. jr in FOUR 320 chunks, one 46KB s_p.
// TILE_JR=16: 80 ring tiles total (half the barriers of R16). Accumulators and
// row sums persist in registers across chunks; 3-stage cp.async ring flows
// continuously across chunk boundaries, ONE __syncthreads per tile.
template <bool LEAKY_OUT>
__global__ __launch_bounds__(256) void attn_kernel() {
    extern __shared__ float sm[];
    float*    s_p    = sm;                               // [320][36] transposed
    float*    s_dst  = s_p + cJQ * P_STRIDE;             // 320 (current chunk)
    float*    s_src  = s_dst + cJQ;                      // 160
    float*    s_inv  = s_src + ATTN_TILE_I * cR;         // 32
    unsigned* s_mask = reinterpret_cast<unsigned*>(s_inv + ATTN_TILE_I); // 320 words
    float*    s_h    = reinterpret_cast<float*>(s_mask + ATTN_TILE_I * MASK_WORDS_Q);
                                                         // 3*16*128 (16B aligned)

    const int b  = blockIdx.x >> 3;
    const int i0 = (blockIdx.x & 7) * ATTN_TILE_I;
    const int t  = threadIdx.x;

    const float* hbase = &g_h[(size_t)b * cJR * cCH];
    const unsigned s_h_addr = (unsigned)__cvta_generic_to_shared(s_h);

    // prefetch tiles 0,1 (16x128 floats = 512 float4 -> 2 cp_async16 per thread)
#pragma unroll
    for (int tt = 0; tt < 2; tt++) {
        const float* src = hbase + tt * TILE_JR * cCH;
        unsigned dst = s_h_addr + (tt % N_STAGES) * (TILE_JR * cCH * 4);
#pragma unroll
        for (int u = 0; u < 2; u++) {
            int idx = t + 256 * u;
            int r = idx >> 5, cc = idx & 31;
            cp_async16(dst + (r * cCH + cc * 4) * 4, src + r * cCH + cc * 4);
        }
        cp_commit();
    }

    if (t < ATTN_TILE_I * cR) s_src[t] = g_src[(b * cN + i0) * cR + t];

    const int p1row = t >> 3, p1l8 = t & 7;   // phase-1 mapping
    unsigned long long acc[4][2];             // phase-2 accumulators (persist chunks)
#pragma unroll
    for (int i = 0; i < 4; i++) { acc[i][0] = 0ull; acc[i][1] = 0ull; }
    float sum = 0.f;                          // row partial sum (persists chunks)

    const int c4 = t & 31;                    // phase-2: cols c4*4..+3
    const int rg = t >> 5;                    // phase-2: warp -> rows rg*4..+3
    const float* pbase = s_p + rg * 4;

    for (int chunk = 0; chunk < 4; chunk++) {
        // load this chunk's dst + mask (s_src loaded once above)
        for (int idx = t; idx < cJQ; idx += 256)
            s_dst[idx] = g_dst[b * cJR + chunk * cJQ + idx];
        for (int idx = t; idx < ATTN_TILE_I * MASK_WORDS_Q; idx += 256)   // 320 words
            s_mask[idx] = g_mask[(b * cN + i0 + (idx / MASK_WORDS_Q)) * MASK_WORDS_PER_ROW
                                 + chunk * MASK_WORDS_Q + (idx % MASK_WORDS_Q)];
        __syncthreads();   // dst/mask ready; also gates s_p reuse (chunk-end bar)

        // ---- phase 1 (8 threads / row): single pass, no max-subtraction
        {
            const float* srcr = s_src + p1row * cR;
            const unsigned* mrow = s_mask + p1row * MASK_WORDS_Q;
            int r = p1l8 % 5;                  // 320 % 5 == 0: local e%5 == global jr%5
            for (int e = p1l8; e < cJQ; e += 8) {
                float v = leaky(srcr[r] + s_dst[e]);
                unsigned bit = (mrow[e >> 5] >> (e & 31)) & 1u;
                float p = bit ? __expf(v) : 0.f;
                s_p[e * P_STRIDE + p1row] = p;
                sum += p;
                r += 3; if (r >= 5) r -= 5;
            }
            if (chunk == 3) {                  // final sum reduce -> s_inv
                float sred = sum;
#pragma unroll
                for (int o = 4; o; o >>= 1) sred += __shfl_xor_sync(0xffffffffu, sred, o);
                if (p1l8 == 0) s_inv[p1row] = 1.f / sred;
            }
        }

        // ---- phase 2 over this chunk's 20 tiles (ring continues across chunks)
        for (int local = 0; local < N_TILES_Q; local++) {
            const int tt = chunk * N_TILES_Q + local;
            cp_wait<1>();
            __syncthreads();   // tile tt ready; phase-1 writes visible; tile tt-1 done
            if (tt + 2 < N_TILES_TOTAL) {
                const int pf = tt + 2;
                const float* src = hbase + pf * TILE_JR * cCH;
                unsigned dst = s_h_addr + (pf % N_STAGES) * (TILE_JR * cCH * 4);
#pragma unroll
                for (int u = 0; u < 2; u++) {
                    int idx = t + 256 * u;
                    int r = idx >> 5, cc = idx & 31;
                    cp_async16(dst + (r * cCH + cc * 4) * 4, src + r * cCH + cc * 4);
                }
            }
            cp_commit();       // exactly one group per iteration

            const float* hh = s_h + (tt % N_STAGES) * (TILE_JR * cCH) + c4 * 4;
            const float* pp = pbase + local * TILE_JR * P_STRIDE;
#pragma unroll
            for (int j = 0; j < TILE_JR; j++) {
                float4 p4 = *reinterpret_cast<const float4*>(pp);  // warp-uniform bcast
                ulonglong2 hv = *reinterpret_cast<const ulonglong2*>(hh);
                unsigned long long pa;
                pa = pack2(p4.x, p4.x); fma2(acc[0][0], pa, hv.x); fma2(acc[0][1], pa, hv.y);
                pa = pack2(p4.y, p4.y); fma2(acc[1][0], pa, hv.x); fma2(acc[1][1], pa, hv.y);
                pa = pack2(p4.z, p4.z); fma2(acc[2][0], pa, hv.x); fma2(acc[2][1], pa, hv.y);
                pa = pack2(p4.w, p4.w); fma2(acc[3][0], pa, hv.x); fma2(acc[3][1], pa, hv.y);
                pp += P_STRIDE;
                hh += cCH;
            }
        }
        __syncthreads();       // all reads of s_p/s_dst done before next chunk rewrites
    }

    // ---- epilogue: normalize by total sums, optional leaky, store
#pragma unroll
    for (int i = 0; i < 4; i++) {
        const int row = rg * 4 + i;
        const float inv = s_inv[row];
        float2 lo = unpack2(acc[i][0]), hi = unpack2(acc[i][1]);
        float4 o = {lo.x * inv, lo.y * inv, hi.x * inv, hi.y * inv};
        if (LEAKY_OUT) {
            o.x = leaky(o.x); o.y = leaky(o.y); o.z = leaky(o.z); o.w = leaky(o.w);
        }
        *reinterpret_cast<float4*>(&g_atoms[(b * cN + i0 + row) * cCH + c4 * 4]) = o;
    }
}

// ---------------- 5) mean/max pooling over nodes ----------------
__global__ __launch_bounds__(512) void pool_kernel() {
    __shared__ float s_sum[4][cCH];
    __shared__ float s_max[4][cCH];
    const int b  = blockIdx.x;
    const int c  = threadIdx.x & 127;
    const int ch = threadIdx.x >> 7;
    float sum = 0.f, mx = -3.4e38f;
    for (int n = ch * 64; n < ch * 64 + 64; n++) {
        float v = g_atoms[(b * cN + n) * cCH + c];
        sum += v;
        mx = fmaxf(mx, v);
    }
    s_sum[ch][c] = sum;
    s_max[ch][c] = mx;
    __syncthreads();
    if (ch == 0) {
        sum = (s_sum[0][c] + s_sum[1][c]) + (s_sum[2][c] + s_sum[3][c]);
        mx = fmaxf(fmaxf(s_max[0][c], s_max[1][c]), fmaxf(s_max[2][c], s_max[3][c]));
        g_pool[b * 256 + c] = sum * (1.f / 256.f);
        g_pool[b * 256 + cCH + c] = mx;
    }
}

// ---------------- 6) final MLP (block per batch) ----------------
__global__ __launch_bounds__(256) void mlp_kernel(const float* __restrict__ x,
                                                  const float* __restrict__ We1, const float* __restrict__ be1,
                                                  const float* __restrict__ We2, const float* __restrict__ be2,
                                                  const float* __restrict__ We3, const float* __restrict__ be3,
                                                  float* __restrict__ out) {
    __shared__ float s_z[cXD + 256];
    __shared__ float s_h1[256];
    __shared__ float s_h2[32];
    const int b = blockIdx.x, t = threadIdx.x;
    for (int i = t; i < cXD; i += 256) s_z[i] = x[b * cXD + i];
    s_z[cXD + t] = g_pool[b * 256 + t];
    __syncthreads();
    {
        float a0 = 0.f, a1 = 0.f, a2 = 0.f, a3 = 0.f;
#pragma unroll 2
        for (int k = 0; k < cXD + 256; k += 4) {
            a0 += s_z[k + 0] * We1[(k + 0) * 256 + t];
            a1 += s_z[k + 1] * We1[(k + 1) * 256 + t];
            a2 += s_z[k + 2] * We1[(k + 2) * 256 + t];
            a3 += s_z[k + 3] * We1[(k + 3) * 256 + t];
        }
        float v = (a0 + a1) + (a2 + a3) + be1[t];
        s_h1[t] = leaky(v);
    }
    __syncthreads();
    if (t < 32) {
        float c0 = 0.f, c1 = 0.f, c2 = 0.f, c3 = 0.f;
        for (int k = 0; k < 256; k += 4) {
            c0 += s_h1[k + 0] * We2[(k + 0) * 32 + t];
            c1 += s_h1[k + 1] * We2[(k + 1) * 32 + t];
            c2 += s_h1[k + 2] * We2[(k + 2) * 32 + t];
            c3 += s_h1[k + 3] * We2[(k + 3) * 32 + t];
        }
        float u = (c0 + c1) + (c2 + c3) + be2[t];
        s_h2[t] = leaky(u);
    }
    __syncthreads();
    if (t < 32) {
        float p = s_h2[t] * We3[t];
#pragma unroll
        for (int o = 16; o; o >>= 1) p += __shfl_xor_sync(0xffffffffu, p, o);
        if (t == 0) out[b] = p + be3[0];
    }
}

// ---------------- launch ----------------
extern "C" void kernel_launch(void* const* d_in, const int* in_sizes, int n_in,
                              void* d_out, int out_size) {
    const float* x       = (const float*)d_in[0];
    const float* y_atoms = (const float*)d_in[1];
    const int*   y_bonds = (const int*)d_in[2];
    const float* W1 = (const float*)d_in[3];
    const float* b1 = (const float*)d_in[4];
    const float* a1 = (const float*)d_in[5];
    const float* W2 = (const float*)d_in[6];
    const float* b2 = (const float*)d_in[7];
    const float* a2 = (const float*)d_in[8];
    const float* W3 = (const float*)d_in[9];
    const float* b3 = (const float*)d_in[10];
    const float* a3 = (const float*)d_in[11];
    const float* We1 = (const float*)d_in[12];
    const float* be1 = (const float*)d_in[13];
    const float* We2 = (const float*)d_in[14];
    const float* be2 = (const float*)d_in[15];
    const float* We3 = (const float*)d_in[16];
    const float* be3 = (const float*)d_in[17];
    float* out = (float*)d_out;

    cudaFuncSetAttribute((const void*)attn_kernel<true>,
                         cudaFuncAttributeMaxDynamicSharedMemorySize, ATTN_SMEM);
    cudaFuncSetAttribute((const void*)attn_kernel<false>,
                         cudaFuncAttributeMaxDynamicSharedMemorySize, ATTN_SMEM);

    float* atoms_ptr = nullptr;
    cudaGetSymbolAddress((void**)&atoms_ptr, g_atoms);

    const dim3 gemm_grid(10, 64);          // 128x64 tiles over 8192x640
    const int attn_grid = cB * N_ITILES;   // 256

    pack_mask_kernel<<<(cB * cN * MASK_WORDS_PER_ROW + 255) / 256, 256>>>(y_bonds);

    // layer 1
    gemm_bias_kernel<cCIN><<<gemm_grid, 256>>>(y_atoms, W1, b1);
    src_dst_kernel<<<cB * cN, 160>>>(a1);
    attn_kernel<true><<<attn_grid, 256, ATTN_SMEM>>>();
    // layer 2
    gemm_bias_kernel<cCH><<<gemm_grid, 256>>>(atoms_ptr, W2, b2);
    src_dst_kernel<<<cB * cN, 160>>>(a2);
    attn_kernel<true><<<attn_grid, 256, ATTN_SMEM>>>();
    // layer 3
    gemm_bias_kernel<cCH><<<gemm_grid, 256>>>(atoms_ptr, W3, b3);
    src_dst_kernel<<<cB * cN, 160>>>(a3);
    attn_kernel<false><<<attn_grid, 256, ATTN_SMEM>>>();

    pool_kernel<<<cB, 512>>>();
    mlp_kernel<<<cB, 256>>>(x, We1, be1, We2, be2, We3, be3, out);
}